// round 5
// baseline (speedup 1.0000x reference)
#include <cuda_runtime.h>
#include <cuda_fp16.h>

static constexpr int NB  = 64;     // batch
static constexpr int PP  = 196;    // spatial positions
static constexpr int EE  = 2048;   // feature dim
static constexpr int DD  = 256;    // hidden
static constexpr int HH  = 256;    // attention hidden
static constexpr int EMB = 256;    // embedding
static constexpr int VV  = 10000;  // vocab
static constexpr int LL  = 32;     // caption length
static constexpr int TT  = 31;     // timesteps
static constexpr int XK  = EMB + EE + DD;  // 2560
static constexpr int G4  = 4 * DD;         // 1024
static constexpr int KC  = 10;             // split-K chunks for gates gemm

__device__ int    g_order[NB];
__device__ int    g_target[NB];
__device__ __half g_fe16[NB * PP * HH];     // 6.4 MB fp16 attention features
__device__ float  g_mean[NB * EE];
__device__ float  g_h[NB * DD];
__device__ float  g_c[NB * DD];
__device__ float  g_score[NB * PP];
__device__ float  g_x[NB * XK];
__device__ float  g_gp[KC * NB * G4];       // split-K partials for gates
__device__ float  g_gatep[2 * NB * EE];     // split-K partials for gate pre-act
__device__ __half g_Wg16[DD * EE];          // W_gate fp16
__device__ __half g_Wih16[XK * G4];         // [W_ih ; W_hh] fp16 concat (2560x1024)
__device__ __half g_Whead16[DD * VV];       // W_head fp16

__device__ __forceinline__ float sigf(float x) { return 1.0f / (1.0f + expf(-x)); }

// ---------------------------------------------------------------------------
// K0: stable descending counting sort of lengths (matches jnp.argsort(-len))
// ---------------------------------------------------------------------------
__global__ void k_order(const int* __restrict__ caplen) {
    if (threadIdx.x == 0) {
        int idx = 0;
        for (int v = LL; v >= 1; --v) {
            for (int i = 0; i < NB; ++i) {
                if (caplen[i] == v) {
                    g_order[idx]  = i;
                    g_target[idx] = v - 1;
                    ++idx;
                }
            }
        }
    }
}

// ---------------------------------------------------------------------------
// K_cvt: one-time fp32 -> fp16 conversion of step-loop weights
// ---------------------------------------------------------------------------
__global__ void k_cvt(const float* __restrict__ Wg, const float* __restrict__ Wih,
                      const float* __restrict__ Whh, const float* __restrict__ Whead) {
    const int NQ_G  = (DD * EE) / 4;        // 131072
    const int NQ_IH = (2304 * G4) / 4;      // 589824
    const int NQ_HH = (DD * G4) / 4;        // 65536
    const int NQ_HD = (DD * VV) / 4;        // 640000
    const int total = NQ_G + NQ_IH + NQ_HH + NQ_HD;
    for (int i = blockIdx.x * blockDim.x + threadIdx.x; i < total;
         i += gridDim.x * blockDim.x) {
        const float* src; __half* dst; int q;
        if (i < NQ_G)                    { src = Wg;    dst = g_Wg16;                 q = i; }
        else if (i < NQ_G + NQ_IH)       { src = Wih;   dst = g_Wih16;                q = i - NQ_G; }
        else if (i < NQ_G + NQ_IH + NQ_HH){ src = Whh;  dst = g_Wih16 + 2304 * G4;    q = i - NQ_G - NQ_IH; }
        else                             { src = Whead; dst = g_Whead16;              q = i - NQ_G - NQ_IH - NQ_HH; }
        float4 v = *(const float4*)(src + (size_t)q * 4);
        *(__half2*)(dst + (size_t)q * 4)     = __floats2half2_rn(v.x, v.y);
        *(__half2*)(dst + (size_t)q * 4 + 2) = __floats2half2_rn(v.z, v.w);
    }
}

// ---------------------------------------------------------------------------
// K3: fused launch, grid (98, 5):
//   blockIdx.y < 4 : fe = feat[order] @ Wf + bf -> fp16. BM=128 BN=64 BK=16.
//   blockIdx.y == 4: mean over positions (blocks 0..63)
// ---------------------------------------------------------------------------
__global__ void __launch_bounds__(256) k_fe(const float* __restrict__ feat,
                                            const float* __restrict__ Wf,
                                            const float* __restrict__ bf) {
    int tid = threadIdx.x;
    int mb = blockIdx.x, nb = blockIdx.y;

    if (nb == 4) {
        if (mb >= NB) return;
        int b = mb;
        const float4* base = (const float4*)(feat + (size_t)g_order[b] * PP * EE);
        float4 sA = make_float4(0.f, 0.f, 0.f, 0.f);
        float4 sB = make_float4(0.f, 0.f, 0.f, 0.f);
        #pragma unroll 2
        for (int p = 0; p < PP; ++p) {
            float4 v0 = __ldcs(base + (size_t)p * (EE / 4) + tid);
            float4 v1 = __ldcs(base + (size_t)p * (EE / 4) + tid + 256);
            sA.x += v0.x; sA.y += v0.y; sA.z += v0.z; sA.w += v0.w;
            sB.x += v1.x; sB.y += v1.y; sB.z += v1.z; sB.w += v1.w;
        }
        const float inv = 1.0f / PP;
        sA.x *= inv; sA.y *= inv; sA.z *= inv; sA.w *= inv;
        sB.x *= inv; sB.y *= inv; sB.z *= inv; sB.w *= inv;
        *(float4*)(g_mean + b * EE + tid * 4)        = sA;
        *(float4*)(g_mean + b * EE + 1024 + tid * 4) = sB;
        return;
    }

    __shared__ float As[16][132];
    __shared__ float Bs[16][64];
    __shared__ size_t rowoff[128];

    if (tid < 128) {
        int gm = mb * 128 + tid;
        int b = gm / PP, p = gm % PP;
        rowoff[tid] = ((size_t)g_order[b] * PP + p) * EE;
    }
    float acc[8][4] = {};
    int rb = (tid >> 4) * 8, cb = (tid & 15) * 4;
    __syncthreads();

    int ar = tid >> 1, ak = (tid & 1) * 8;
    int bk = tid >> 4, bn = (tid & 15) * 4;

    for (int k0 = 0; k0 < EE; k0 += 16) {
        {
            const float* src = feat + rowoff[ar] + k0 + ak;
            float4 a0 = *(const float4*)(src);
            float4 a1 = *(const float4*)(src + 4);
            As[ak + 0][ar] = a0.x; As[ak + 1][ar] = a0.y;
            As[ak + 2][ar] = a0.z; As[ak + 3][ar] = a0.w;
            As[ak + 4][ar] = a1.x; As[ak + 5][ar] = a1.y;
            As[ak + 6][ar] = a1.z; As[ak + 7][ar] = a1.w;
        }
        {
            *(float4*)&Bs[bk][bn] = *(const float4*)(Wf + (size_t)(k0 + bk) * HH + nb * 64 + bn);
        }
        __syncthreads();
        #pragma unroll
        for (int kk = 0; kk < 16; ++kk) {
            float a[8], bv[4];
            *(float4*)(a)     = *(float4*)&As[kk][rb];
            *(float4*)(a + 4) = *(float4*)&As[kk][rb + 4];
            *(float4*)(bv)    = *(float4*)&Bs[kk][cb];
            #pragma unroll
            for (int i = 0; i < 8; ++i)
                #pragma unroll
                for (int j = 0; j < 4; ++j) acc[i][j] += a[i] * bv[j];
        }
        __syncthreads();
    }
    #pragma unroll
    for (int i = 0; i < 8; ++i) {
        int gm = mb * 128 + rb + i;
        int gn = nb * 64 + cb;
        __half2 h01 = __floats2half2_rn(acc[i][0] + bf[gn + 0], acc[i][1] + bf[gn + 1]);
        __half2 h23 = __floats2half2_rn(acc[i][2] + bf[gn + 2], acc[i][3] + bf[gn + 3]);
        *(__half2*)(g_fe16 + (size_t)gm * HH + gn)     = h01;
        *(__half2*)(g_fe16 + (size_t)gm * HH + gn + 2) = h23;
    }
}

// ---------------------------------------------------------------------------
// K2: h0 = mean @ W_hid + b_hid ; c0 = mean @ W_cell + b_cell
// ---------------------------------------------------------------------------
__global__ void k_init(const float* __restrict__ W_hid, const float* __restrict__ b_hid,
                       const float* __restrict__ W_cell, const float* __restrict__ b_cell) {
    int b = blockIdx.x, j = threadIdx.x;
    __shared__ float sm[EE];
    for (int e = j; e < EE; e += 256) sm[e] = g_mean[b * EE + e];
    __syncthreads();
    float h = b_hid[j], c = b_cell[j];
    #pragma unroll 4
    for (int e = 0; e < EE; ++e) {
        float m = sm[e];
        h += m * W_hid[e * DD + j];
        c += m * W_cell[e * DD + j];
    }
    g_h[b * DD + j] = h;
    g_c[b * DD + j] = c;
}

// ---------------------------------------------------------------------------
// K4 (per step): ONE launch, three independent jobs:
//   blocks [0,128):   attention scores (2 blocks per batch row, 98 p each)
//   blocks [128,192): gate-pre GEMM h @ W_gate16, split-K=2
//   blocks [192,349): head GEMM for step t-1 with W_head16
// ---------------------------------------------------------------------------
__global__ void __launch_bounds__(256) k_stepA(
        const float* __restrict__ Wh, const float* __restrict__ bh,
        const float* __restrict__ We, const float* __restrict__ be,
        const float* __restrict__ b_head,
        int t, float* __restrict__ out) {
    int tid = threadIdx.x;
    if (blockIdx.x < 2 * NB) {
        // ---- attention scores: b = idx/2, positions [half*98, half*98+98) ----
        int b = blockIdx.x >> 1, half = blockIdx.x & 1;
        int lane = tid & 31, wid = tid >> 5;
        __shared__ float sh[DD], she[HH], swe[HH];

        sh[tid] = g_h[b * DD + tid];
        swe[tid] = We[tid];
        __syncthreads();

        float acc = bh[tid];
        #pragma unroll 8
        for (int k = 0; k < DD; ++k) acc += sh[k] * Wh[k * HH + tid];
        she[tid] = acc;
        __syncthreads();

        float be0 = be[0];
        int p0 = half * 98, p1 = p0 + 98;
        const __half* febase = g_fe16 + (size_t)b * PP * HH;
        for (int p = p0 + wid; p < p1; p += 8) {
            const __half* fr = febase + (size_t)p * HH;
            float s = 0.f;
            #pragma unroll
            for (int it = 0; it < 4; ++it) {
                int j = it * 64 + lane * 2;
                float2 fv = __half22float2(*(const __half2*)(fr + j));
                float v0 = fv.x + she[j], v1 = fv.y + she[j + 1];
                s += fmaxf(v0, 0.f) * swe[j] + fmaxf(v1, 0.f) * swe[j + 1];
            }
            #pragma unroll
            for (int o = 16; o; o >>= 1) s += __shfl_xor_sync(0xffffffffu, s, o);
            if (lane == 0) g_score[b * PP + p] = s + be0;
        }
    } else if (blockIdx.x < 3 * NB) {
        // ---- h @ W_gate16 (64 x 256 x 2048), split-K=2 ----
        __shared__ float As[16][68];
        __shared__ float Bs[16][64];
        int bid = blockIdx.x - 2 * NB;
        int nb = bid & 31, kc = bid >> 5;
        int kbase = kc * 128;
        float acc[4][4] = {};
        int rb = (tid >> 4) * 4, cb = (tid & 15) * 4;

        for (int kt = 0; kt < 128; kt += 16) {
            {
                int r = tid >> 2, kk = (tid & 3) * 4;
                float4 av = *(const float4*)(g_h + r * DD + kbase + kt + kk);
                As[kk + 0][r] = av.x; As[kk + 1][r] = av.y;
                As[kk + 2][r] = av.z; As[kk + 3][r] = av.w;
            }
            {
                int kk = tid >> 4, n = (tid & 15) * 4;
                const __half* src = g_Wg16 + (size_t)(kbase + kt + kk) * EE + nb * 64 + n;
                float2 f0 = __half22float2(*(const __half2*)(src));
                float2 f1 = __half22float2(*(const __half2*)(src + 2));
                Bs[kk][n + 0] = f0.x; Bs[kk][n + 1] = f0.y;
                Bs[kk][n + 2] = f1.x; Bs[kk][n + 3] = f1.y;
            }
            __syncthreads();
            #pragma unroll
            for (int kk = 0; kk < 16; ++kk) {
                float a[4], bv[4];
                *(float4*)a  = *(float4*)&As[kk][rb];
                *(float4*)bv = *(float4*)&Bs[kk][cb];
                #pragma unroll
                for (int i = 0; i < 4; ++i)
                    #pragma unroll
                    for (int j = 0; j < 4; ++j) acc[i][j] += a[i] * bv[j];
            }
            __syncthreads();
        }
        #pragma unroll
        for (int i = 0; i < 4; ++i)
            #pragma unroll
            for (int j = 0; j < 4; ++j)
                g_gatep[((size_t)kc * NB + rb + i) * EE + nb * 64 + cb + j] = acc[i][j];
    } else {
        // ---- head GEMM for step t-1 with fp16 weights ----
        int tprev = t - 1;
        __shared__ float As[16][68];
        __shared__ float Bs[16][64];
        int nb = blockIdx.x - 3 * NB;
        int n0 = nb * 64;
        float acc[4][4] = {};
        int rb = (tid >> 4) * 4, cb = (tid & 15) * 4;

        for (int k0 = 0; k0 < DD; k0 += 16) {
            {
                int r = tid >> 2, kk = (tid & 3) * 4;
                float4 av = *(const float4*)(g_h + r * DD + k0 + kk);
                As[kk + 0][r] = av.x; As[kk + 1][r] = av.y;
                As[kk + 2][r] = av.z; As[kk + 3][r] = av.w;
            }
            {
                int kk = tid >> 4, n = (tid & 15) * 4;
                int gn = n0 + n;
                const __half* src = g_Whead16 + (size_t)(k0 + kk) * VV + gn;
                float b0, b1, b2, b3;
                if (gn + 3 < VV) {
                    float2 f0 = __half22float2(*(const __half2*)(src));
                    float2 f1 = __half22float2(*(const __half2*)(src + 2));
                    b0 = f0.x; b1 = f0.y; b2 = f1.x; b3 = f1.y;
                } else {
                    b0 = (gn + 0 < VV) ? __half2float(src[0]) : 0.f;
                    b1 = (gn + 1 < VV) ? __half2float(src[1]) : 0.f;
                    b2 = (gn + 2 < VV) ? __half2float(src[2]) : 0.f;
                    b3 = (gn + 3 < VV) ? __half2float(src[3]) : 0.f;
                }
                Bs[kk][n + 0] = b0; Bs[kk][n + 1] = b1;
                Bs[kk][n + 2] = b2; Bs[kk][n + 3] = b3;
            }
            __syncthreads();
            #pragma unroll
            for (int kk = 0; kk < 16; ++kk) {
                float a[4], bv[4];
                *(float4*)a  = *(float4*)&As[kk][rb];
                *(float4*)bv = *(float4*)&Bs[kk][cb];
                #pragma unroll
                for (int i = 0; i < 4; ++i)
                    #pragma unroll
                    for (int j = 0; j < 4; ++j) acc[i][j] += a[i] * bv[j];
            }
            __syncthreads();
        }
        #pragma unroll
        for (int i = 0; i < 4; ++i) {
            int b = rb + i;
            bool msk = (g_target[b] > tprev);
            size_t rowbase = ((size_t)b * TT + tprev) * VV;
            #pragma unroll
            for (int j = 0; j < 4; ++j) {
                int gn = n0 + cb + j;
                if (gn < VV) out[rowbase + gn] = msk ? (acc[i][j] + b_head[gn]) : 0.f;
            }
        }
    }
}

// ---------------------------------------------------------------------------
// K6 (per step): softmax(scores) + ctx scan + assemble x. grid (NB,4), 128 thr.
// ---------------------------------------------------------------------------
__global__ void __launch_bounds__(128) k_ctx(
        const float* __restrict__ feat, const float* __restrict__ b_gate,
        const float* __restrict__ emb, const int* __restrict__ tok, int t,
        float* __restrict__ out_att) {
    int b = blockIdx.x, tid = threadIdx.x;
    int lane = tid & 31, wid = tid >> 5;
    __shared__ float sw[PP];
    __shared__ float red[4];

    // ---- softmax over 196 scores ----
    float v0 = g_score[b * PP + tid];
    float v1 = (tid + 128 < PP) ? g_score[b * PP + tid + 128] : -3.4e38f;
    float m = fmaxf(v0, v1);
    #pragma unroll
    for (int o = 16; o; o >>= 1) m = fmaxf(m, __shfl_xor_sync(0xffffffffu, m, o));
    if (lane == 0) red[wid] = m;
    __syncthreads();
    if (tid == 0) {
        float mm = fmaxf(fmaxf(red[0], red[1]), fmaxf(red[2], red[3]));
        red[0] = mm;
    }
    __syncthreads();
    float mx = red[0];
    __syncthreads();

    float e0 = expf(v0 - mx);
    float e1 = (tid + 128 < PP) ? expf(v1 - mx) : 0.f;
    float s = e0 + e1;
    #pragma unroll
    for (int o = 16; o; o >>= 1) s += __shfl_xor_sync(0xffffffffu, s, o);
    if (lane == 0) red[wid] = s;
    __syncthreads();
    if (tid == 0) red[0] = (red[0] + red[1]) + (red[2] + red[3]);
    __syncthreads();
    float inv = 1.0f / red[0];
    sw[tid] = e0 * inv;
    if (tid + 128 < PP) sw[tid + 128] = e1 * inv;
    __syncthreads();

    if (blockIdx.y == 0) {
        bool msk = (g_target[b] > t);
        out_att[((size_t)b * TT + t) * PP + tid] = msk ? sw[tid] : 0.f;
        if (tid + 128 < PP)
            out_att[((size_t)b * TT + t) * PP + tid + 128] = msk ? sw[tid + 128] : 0.f;
    }

    // ---- ctx scan ----
    int e0i = blockIdx.y * 512 + tid * 4;
    const float4* fb = (const float4*)(feat + (size_t)g_order[b] * PP * EE + e0i);

    float4 s0 = make_float4(0.f, 0.f, 0.f, 0.f);
    float4 s1 = make_float4(0.f, 0.f, 0.f, 0.f);
    float4 s2 = make_float4(0.f, 0.f, 0.f, 0.f);
    float4 s3 = make_float4(0.f, 0.f, 0.f, 0.f);
    for (int p = 0; p < PP; p += 4) {
        float w0 = sw[p], w1 = sw[p + 1], w2 = sw[p + 2], w3 = sw[p + 3];
        float4 f0 = __ldcs(fb + (size_t)(p + 0) * (EE / 4));
        float4 f1 = __ldcs(fb + (size_t)(p + 1) * (EE / 4));
        float4 f2 = __ldcs(fb + (size_t)(p + 2) * (EE / 4));
        float4 f3 = __ldcs(fb + (size_t)(p + 3) * (EE / 4));
        s0.x += w0 * f0.x; s0.y += w0 * f0.y; s0.z += w0 * f0.z; s0.w += w0 * f0.w;
        s1.x += w1 * f1.x; s1.y += w1 * f1.y; s1.z += w1 * f1.z; s1.w += w1 * f1.w;
        s2.x += w2 * f2.x; s2.y += w2 * f2.y; s2.z += w2 * f2.z; s2.w += w2 * f2.w;
        s3.x += w3 * f3.x; s3.y += w3 * f3.y; s3.z += w3 * f3.z; s3.w += w3 * f3.w;
    }
    float4 sum;
    sum.x = (s0.x + s1.x) + (s2.x + s3.x);
    sum.y = (s0.y + s1.y) + (s2.y + s3.y);
    sum.z = (s0.z + s1.z) + (s2.z + s3.z);
    sum.w = (s0.w + s1.w) + (s2.w + s3.w);

    float4 gp0 = *(const float4*)(g_gatep + (size_t)b * EE + e0i);
    float4 gp1 = *(const float4*)(g_gatep + ((size_t)NB + b) * EE + e0i);
    float4 bg  = *(const float4*)(b_gate + e0i);
    float4 ctx;
    ctx.x = sum.x * sigf(bg.x + gp0.x + gp1.x);
    ctx.y = sum.y * sigf(bg.y + gp0.y + gp1.y);
    ctx.z = sum.z * sigf(bg.z + gp0.z + gp1.z);
    ctx.w = sum.w * sigf(bg.w + gp0.w + gp1.w);
    *(float4*)(g_x + (size_t)b * XK + EMB + e0i) = ctx;

    if (blockIdx.y == 0) {
        int token = tok[g_order[b] * LL + t];
        g_x[b * XK + tid] = emb[(size_t)token * EMB + tid];
        g_x[b * XK + tid + 128] = emb[(size_t)token * EMB + tid + 128];
        g_x[b * XK + EMB + EE + tid] = g_h[b * DD + tid];
        g_x[b * XK + EMB + EE + tid + 128] = g_h[b * DD + tid + 128];
    }
}

// ---------------------------------------------------------------------------
// K7 (per step): gates GEMM  x(64x2560) @ [W_ih;W_hh]16(2560x1024), split-K=10.
// ---------------------------------------------------------------------------
__global__ void k_gates() {
    __shared__ float As[16][68];
    __shared__ float Bs[16][64];
    int tid = threadIdx.x;
    int nb = blockIdx.x, kc = blockIdx.y;
    int k0g = kc * 256;
    const __half* wbase = g_Wih16 + (size_t)k0g * G4;
    float acc[4][4] = {};
    int rb = (tid >> 4) * 4, cb = (tid & 15) * 4;

    for (int kt = 0; kt < 256; kt += 16) {
        {
            int r = tid >> 2, kk = (tid & 3) * 4;
            float4 av = *(const float4*)(g_x + r * XK + k0g + kt + kk);
            As[kk + 0][r] = av.x; As[kk + 1][r] = av.y;
            As[kk + 2][r] = av.z; As[kk + 3][r] = av.w;
        }
        {
            int kk = tid >> 4, n = (tid & 15) * 4;
            const __half* src = wbase + (size_t)(kt + kk) * G4 + nb * 64 + n;
            float2 f0 = __half22float2(*(const __half2*)(src));
            float2 f1 = __half22float2(*(const __half2*)(src + 2));
            Bs[kk][n + 0] = f0.x; Bs[kk][n + 1] = f0.y;
            Bs[kk][n + 2] = f1.x; Bs[kk][n + 3] = f1.y;
        }
        __syncthreads();
        #pragma unroll
        for (int kk = 0; kk < 16; ++kk) {
            float a[4], bv[4];
            *(float4*)a  = *(float4*)&As[kk][rb];
            *(float4*)bv = *(float4*)&Bs[kk][cb];
            #pragma unroll
            for (int i = 0; i < 4; ++i)
                #pragma unroll
                for (int j = 0; j < 4; ++j) acc[i][j] += a[i] * bv[j];
        }
        __syncthreads();
    }
    #pragma unroll
    for (int i = 0; i < 4; ++i)
        #pragma unroll
        for (int j = 0; j < 4; ++j)
            g_gp[((size_t)kc * NB + rb + i) * G4 + nb * 64 + cb + j] = acc[i][j];
}

// ---------------------------------------------------------------------------
// K8 (per step): LSTM pointwise (sums split-K partials + biases; masked update)
// ---------------------------------------------------------------------------
__global__ void k_lstm(const float* __restrict__ b_ih, const float* __restrict__ b_hh, int t) {
    int b = blockIdx.x, j = threadIdx.x;
    float gi = b_ih[j] + b_hh[j];
    float gf = b_ih[DD + j] + b_hh[DD + j];
    float gg = b_ih[2 * DD + j] + b_hh[2 * DD + j];
    float go = b_ih[3 * DD + j] + b_hh[3 * DD + j];
    #pragma unroll
    for (int kc = 0; kc < KC; ++kc) {
        const float* p = g_gp + ((size_t)kc * NB + b) * G4;
        gi += p[j];
        gf += p[DD + j];
        gg += p[2 * DD + j];
        go += p[3 * DD + j];
    }
    float c = g_c[b * DD + j];
    float cn = sigf(gf) * c + sigf(gi) * tanhf(gg);
    float hn = sigf(go) * tanhf(cn);
    if (g_target[b] > t) {
        g_h[b * DD + j] = hn;
        g_c[b * DD + j] = cn;
    }
}

// ---------------------------------------------------------------------------
// K9: standalone head GEMM (only final step t = TT-1), fp16 weights
// ---------------------------------------------------------------------------
__global__ void __launch_bounds__(256) k_head(
        const float* __restrict__ b_head, int t, float* __restrict__ out) {
    __shared__ float As[16][68];
    __shared__ float Bs[16][64];
    int tid = threadIdx.x, nb = blockIdx.x;
    int n0 = nb * 64;
    float acc[4][4] = {};
    int rb = (tid >> 4) * 4, cb = (tid & 15) * 4;

    for (int k0 = 0; k0 < DD; k0 += 16) {
        {
            int r = tid >> 2, kk = (tid & 3) * 4;
            float4 av = *(const float4*)(g_h + r * DD + k0 + kk);
            As[kk + 0][r] = av.x; As[kk + 1][r] = av.y;
            As[kk + 2][r] = av.z; As[kk + 3][r] = av.w;
        }
        {
            int kk = tid >> 4, n = (tid & 15) * 4;
            int gn = n0 + n;
            const __half* src = g_Whead16 + (size_t)(k0 + kk) * VV + gn;
            float b0, b1, b2, b3;
            if (gn + 3 < VV) {
                float2 f0 = __half22float2(*(const __half2*)(src));
                float2 f1 = __half22float2(*(const __half2*)(src + 2));
                b0 = f0.x; b1 = f0.y; b2 = f1.x; b3 = f1.y;
            } else {
                b0 = (gn + 0 < VV) ? __half2float(src[0]) : 0.f;
                b1 = (gn + 1 < VV) ? __half2float(src[1]) : 0.f;
                b2 = (gn + 2 < VV) ? __half2float(src[2]) : 0.f;
                b3 = (gn + 3 < VV) ? __half2float(src[3]) : 0.f;
            }
            Bs[kk][n + 0] = b0; Bs[kk][n + 1] = b1;
            Bs[kk][n + 2] = b2; Bs[kk][n + 3] = b3;
        }
        __syncthreads();
        #pragma unroll
        for (int kk = 0; kk < 16; ++kk) {
            float a[4], bv[4];
            *(float4*)a  = *(float4*)&As[kk][rb];
            *(float4*)bv = *(float4*)&Bs[kk][cb];
            #pragma unroll
            for (int i = 0; i < 4; ++i)
                #pragma unroll
                for (int j = 0; j < 4; ++j) acc[i][j] += a[i] * bv[j];
        }
        __syncthreads();
    }
    #pragma unroll
    for (int i = 0; i < 4; ++i) {
        int b = rb + i;
        bool msk = (g_target[b] > t);
        size_t rowbase = ((size_t)b * TT + t) * VV;
        #pragma unroll
        for (int j = 0; j < 4; ++j) {
            int gn = n0 + cb + j;
            if (gn < VV) out[rowbase + gn] = msk ? (acc[i][j] + b_head[gn]) : 0.f;
        }
    }
}

// ---------------------------------------------------------------------------
extern "C" void kernel_launch(void* const* d_in, const int* in_sizes, int n_in,
                              void* d_out, int out_size) {
    const float* feat   = (const float*)d_in[0];
    const int*   tok    = (const int*)d_in[1];
    const int*   caplen = (const int*)d_in[2];
    const float* Wf     = (const float*)d_in[3];
    const float* bf     = (const float*)d_in[4];
    const float* Wh     = (const float*)d_in[5];
    const float* bh     = (const float*)d_in[6];
    const float* We     = (const float*)d_in[7];
    const float* be     = (const float*)d_in[8];
    const float* emb    = (const float*)d_in[9];
    const float* W_ih   = (const float*)d_in[10];
    const float* b_ih   = (const float*)d_in[11];
    const float* W_hh   = (const float*)d_in[12];
    const float* b_hh   = (const float*)d_in[13];
    const float* W_hid  = (const float*)d_in[14];
    const float* b_hid  = (const float*)d_in[15];
    const float* W_cell = (const float*)d_in[16];
    const float* b_cell = (const float*)d_in[17];
    const float* W_gate = (const float*)d_in[18];
    const float* b_head = (const float*)d_in[21];

    float* out = (float*)d_out;
    float* out_att = out + (size_t)NB * TT * VV;

    k_order<<<1, 32>>>(caplen);
    k_cvt<<<512, 256>>>(W_gate, W_ih, W_hh, (const float*)d_in[20]);
    k_fe<<<dim3(98, 5), 256>>>(feat, Wf, bf);   // fe GEMM (fp16 out) + mean
    k_init<<<NB, 256>>>(W_hid, b_hid, W_cell, b_cell);

    for (int t = 0; t < TT; ++t) {
        // scores(t) + gpre(t) + head(t-1) in one launch (t=0: no head blocks)
        int nblk = (t == 0) ? 3 * NB : 3 * NB + 157;
        k_stepA<<<nblk, 256>>>(Wh, bh, We, be, b_head, t, out);
        k_ctx<<<dim3(NB, 4), 128>>>(feat, (const float*)d_in[19], emb, tok, t, out_att);
        k_gates<<<dim3(16, 10), 256>>>();
        k_lstm<<<NB, 256>>>(b_ih, b_hh, t);
    }
    k_head<<<157, 256>>>(b_head, TT - 1, out);
}